// round 7
// baseline (speedup 1.0000x reference)
#include <cuda_runtime.h>

#define BB    4
#define NN    8192
#define ALPHA 5.0f
#define EPS   1e-12f

#define SPLIT  8                 // ref-dimension split
#define SLICE  (NN / SPLIT)      // 1024 refs per block
#define SLICEP (SLICE / 2)       // 512 ref pairs (16 KB smem)
#define QB     128               // threads per block
#define QPT    2                 // queries per thread
#define QBLK   (QB * QPT)        // 256 queries per block
#define GX     (NN / QBLK)       // 32 query-groups per batch

typedef unsigned long long ull;

__device__ float g_part[BB * SPLIT * NN];  // per-(batch,slice,query) partial min
__device__ float g_dsum[BB * NN];
__device__ float g_bsum[BB];               // self-resetting accumulators
__device__ float g_loss;
__device__ int   g_done_q[BB * GX];        // slice-completion counters (self-resetting)
__device__ int   g_done_b[BB];
__device__ int   g_alldone;

__device__ __forceinline__ ull f2u(float a, float b) {
    union { float f[2]; ull u; } t; t.f[0] = a; t.f[1] = b; return t.u;
}
__device__ __forceinline__ void u2f(ull v, float& a, float& b) {
    union { float f[2]; ull u; } t; t.u = v; a = t.f[0]; b = t.f[1];
}
__device__ __forceinline__ ull fma2(ull a, ull b, ull c) {
    ull d; asm("fma.rn.f32x2 %0, %1, %2, %3;" : "=l"(d) : "l"(a), "l"(b), "l"(c)); return d;
}

__device__ __forceinline__ float block_reduce_sum(float v) {
    __shared__ float sh[QB / 32];
    int lane = threadIdx.x & 31;
    int wid  = threadIdx.x >> 5;
    #pragma unroll
    for (int o = 16; o; o >>= 1) v += __shfl_down_sync(0xFFFFFFFFu, v, o);
    if (lane == 0) sh[wid] = v;
    __syncthreads();
    v = (threadIdx.x < QB / 32) ? sh[threadIdx.x] : 0.0f;
    if (wid == 0) {
        #pragma unroll
        for (int o = (QB / 64); o; o >>= 1) v += __shfl_down_sync(0xFFFFFFFFu, v, o);
    }
    return v;   // valid in thread 0
}

// One launch does everything:
//  phase 1: slice scan -> per-query partial min (2-min excl-self in self blocks)
//  phase 2 (last of 8 slice-blocks per query-group): merge + dsum + batch sum
//  phase 3 (last of 32 groups per batch): masked loss for the batch
//  phase 4 (last of 4 batches): write out[0]; all counters/accums self-reset.
__global__ void __launch_bounds__(QB) k_all(const float* __restrict__ xyz,
                                            float* __restrict__ out) {
    __shared__ float4 sA[SLICEP];   // {x0,x1,y0,y1} per ref pair
    __shared__ float4 sB[SLICEP];   // {z0,z1,w0,w1}
    __shared__ int    sh_flag;

    const int b     = blockIdx.y;
    const int slice = blockIdx.z;
    const int tid   = threadIdx.x;

    // ---- load + pack this block's ref slice from raw xyz ----
    const float* __restrict__ src = xyz + (size_t)(b * NN + slice * SLICE) * 3;
    #pragma unroll
    for (int k = 0; k < SLICEP / QB; k++) {          // 4 pairs/thread
        int q = tid + k * QB;
        float x0 = src[6*q+0], y0 = src[6*q+1], z0 = src[6*q+2];
        float x1 = src[6*q+3], y1 = src[6*q+4], z1 = src[6*q+5];
        float w0 = (x0*x0 + y0*y0) + z0*z0;
        float w1 = (x1*x1 + y1*y1) + z1*z1;
        sA[q] = make_float4(x0, x1, y0, y1);
        sB[q] = make_float4(z0, z1, w0, w1);
    }

    const int qbase = blockIdx.x * QBLK + tid;
    ull mx[QPT], my[QPT], mz[QPT];
    #pragma unroll
    for (int k = 0; k < QPT; k++) {
        const float* qp = xyz + (size_t)(b * NN + qbase + k * QB) * 3;
        float qx = qp[0], qy = qp[1], qz = qp[2];
        mx[k] = f2u(-2.0f*qx, -2.0f*qx);
        my[k] = f2u(-2.0f*qy, -2.0f*qy);
        mz[k] = f2u(-2.0f*qz, -2.0f*qz);
    }

    __syncthreads();

    const bool self_block = (slice == (blockIdx.x >> 2));  // QBLK*4 == SLICE
    float part[QPT];

    if (!self_block) {
        // fast path: plain min, 4 independent accumulators per query
        float a0[QPT], a1[QPT], a2[QPT], a3[QPT];
        #pragma unroll
        for (int k = 0; k < QPT; k++) { a0[k]=a1[k]=a2[k]=a3[k]=3.4e38f; }

        #pragma unroll 4
        for (int j = 0; j < SLICEP; j += 2) {
            float4 A0 = sA[j],   B0 = sB[j];
            float4 A1 = sA[j+1], B1 = sB[j+1];
            ull x0 = f2u(A0.x, A0.y), y0 = f2u(A0.z, A0.w);
            ull z0 = f2u(B0.x, B0.y), w0 = f2u(B0.z, B0.w);
            ull x1 = f2u(A1.x, A1.y), y1 = f2u(A1.z, A1.w);
            ull z1 = f2u(B1.x, B1.y), w1 = f2u(B1.z, B1.w);
            #pragma unroll
            for (int k = 0; k < QPT; k++) {
                ull t0 = fma2(mx[k], x0, fma2(my[k], y0, fma2(mz[k], z0, w0)));
                ull t1 = fma2(mx[k], x1, fma2(my[k], y1, fma2(mz[k], z1, w1)));
                float c0, c1, c2, c3;
                u2f(t0, c0, c1); u2f(t1, c2, c3);
                a0[k] = fminf(a0[k], c0);
                a1[k] = fminf(a1[k], c1);
                a2[k] = fminf(a2[k], c2);
                a3[k] = fminf(a3[k], c3);
            }
        }
        #pragma unroll
        for (int k = 0; k < QPT; k++)
            part[k] = fminf(fminf(a0[k], a1[k]), fminf(a2[k], a3[k]));
    } else {
        // self path: exact 2-min; emit second smallest (min excluding self)
        float s0[QPT], s1[QPT];
        #pragma unroll
        for (int k = 0; k < QPT; k++) { s0[k] = 3.4e38f; s1[k] = 3.4e38f; }

        #pragma unroll 2
        for (int j = 0; j < SLICEP; j += 2) {
            float4 A0 = sA[j],   B0 = sB[j];
            float4 A1 = sA[j+1], B1 = sB[j+1];
            ull x0 = f2u(A0.x, A0.y), y0 = f2u(A0.z, A0.w);
            ull z0 = f2u(B0.x, B0.y), w0 = f2u(B0.z, B0.w);
            ull x1 = f2u(A1.x, A1.y), y1 = f2u(A1.z, A1.w);
            ull z1 = f2u(B1.x, B1.y), w1 = f2u(B1.z, B1.w);
            #pragma unroll
            for (int k = 0; k < QPT; k++) {
                ull t0 = fma2(mx[k], x0, fma2(my[k], y0, fma2(mz[k], z0, w0)));
                ull t1 = fma2(mx[k], x1, fma2(my[k], y1, fma2(mz[k], z1, w1)));
                float c0, c1, c2, c3;
                u2f(t0, c0, c1); u2f(t1, c2, c3);
                float m1 = fminf(c0, c1), M1 = fmaxf(c0, c1);
                float m2 = fminf(c2, c3), M2 = fmaxf(c2, c3);
                float v0 = fminf(m1, m2);
                float v1 = fminf(fmaxf(m1, m2), fminf(M1, M2));
                float n0 = fminf(v0, s0[k]);
                float tt = fmaxf(v0, s0[k]);
                float uu = fminf(v1, s1[k]);
                s0[k] = n0; s1[k] = fminf(tt, uu);
            }
        }
        #pragma unroll
        for (int k = 0; k < QPT; k++) part[k] = s1[k];
    }

    {
        float* dst = &g_part[(b * SPLIT + slice) * NN];
        #pragma unroll
        for (int k = 0; k < QPT; k++) dst[qbase + k * QB] = part[k];
    }

    // ---- phase 2 gate: last of the 8 slice-blocks for this query-group ----
    __threadfence();
    if (tid == 0) {
        int idx = b * GX + blockIdx.x;
        int d = atomicAdd(&g_done_q[idx], 1);
        sh_flag = (d == SPLIT - 1);
        if (d == SPLIT - 1) g_done_q[idx] = 0;     // self-reset for next call
    }
    __syncthreads();
    if (!sh_flag) return;
    __threadfence();   // acquire: see all 8 slices' g_part writes

    // merge 8 partials for this block's 256 queries; dsum + local batch sum
    const int q0 = blockIdx.x * QBLK;
    float local = 0.0f;
    #pragma unroll
    for (int k = 0; k < QPT; k++) {
        int q = q0 + tid + k * QB;
        float m = g_part[(b * SPLIT + 0) * NN + q];
        #pragma unroll
        for (int s = 1; s < SPLIT; s++)
            m = fminf(m, g_part[(b * SPLIT + s) * NN + q]);

        const float* p = xyz + (size_t)(b * NN + q) * 3;
        float px = p[0], py = p[1], pz = p[2];
        float w = (px*px + py*py) + pz*pz;
        float d2nn = w + m;
        float mself = fmaf(-2.0f*px, px, fmaf(-2.0f*py, py, fmaf(-2.0f*pz, pz, w)));
        float d2self = w + mself;

        float ds = sqrtf(fmaxf(d2self, EPS)) + sqrtf(fmaxf(d2nn, EPS));
        g_dsum[b * NN + q] = ds;
        local += ds;
    }
    float t = block_reduce_sum(local);

    // ---- phase 3 gate: last of the 32 merge-blocks for this batch ----
    if (tid == 0) {
        atomicAdd(&g_bsum[b], t);
        __threadfence();
        int d = atomicAdd(&g_done_b[b], 1);
        sh_flag = (d == GX - 1);
        if (d == GX - 1) g_done_b[b] = 0;
    }
    __syncthreads();
    if (!sh_flag) return;
    __threadfence();

    float total = atomicAdd(&g_bsum[b], 0.0f);     // coherent read of batch sum
    float thr = (total / (float)NN) * ALPHA;       // mean first, *ALPHA (ref order)
    float s = 0.0f;
    for (int j = tid; j < NN; j += QB) {
        float d = g_dsum[b * NN + j];
        if (d > thr) s += d;
    }
    s = block_reduce_sum(s);

    // ---- phase 4 gate: last of the 4 batch-loss blocks writes out ----
    if (tid == 0) {
        g_bsum[b] = 0.0f;                          // self-reset
        atomicAdd(&g_loss, s);
        __threadfence();
        int d = atomicAdd(&g_alldone, 1);
        if (d == BB - 1) {
            g_alldone = 0;
            float tot = atomicAdd(&g_loss, 0.0f);  // includes all BB adds
            out[0] = tot;
            g_loss = 0.0f;                         // self-reset
            __threadfence();
        }
    }
}

extern "C" void kernel_launch(void* const* d_in, const int* in_sizes, int n_in,
                              void* d_out, int out_size) {
    const float* xyz = (const float*)d_in[0];
    float* out = (float*)d_out;

    dim3 grid(GX, BB, SPLIT);            // 32 x 4 x 8 = 1024 blocks, one wave
    k_all<<<grid, QB>>>(xyz, out);
}

// round 8
// speedup vs baseline: 1.1994x; 1.1994x over previous
#include <cuda_runtime.h>

#define BB    4
#define NN    8192
#define ALPHA 5.0f
#define EPS   1e-12f

#define SPLIT  16                // ref-dimension split
#define SLICE  (NN / SPLIT)      // 512 refs per block
#define SLICEP (SLICE / 2)       // 256 ref pairs (8 KB smem)
#define QB     128               // threads per knn block
#define QPT    2                 // queries per thread
#define QBLK   (QB * QPT)        // 256 queries per block
#define GX     (NN / QBLK)       // 32 query-groups per batch

typedef unsigned long long ull;
typedef unsigned int uint;

// Reversed-order float keys: min over floats == max over keys; 0 = identity.
__device__ uint g_key[BB * NN];   // zero-initialized at load; finish resets

__device__ __forceinline__ uint rkey(float f) {
    uint b = __float_as_uint(f);
    uint u = (b & 0x80000000u) ? ~b : (b | 0x80000000u);  // ascending order
    return ~u;                                            // descending
}
__device__ __forceinline__ float unrkey(uint r) {
    uint u = ~r;
    uint b = (u & 0x80000000u) ? (u & 0x7FFFFFFFu) : ~u;
    return __uint_as_float(b);
}

__device__ __forceinline__ ull f2u(float a, float b) {
    union { float f[2]; ull u; } t; t.f[0] = a; t.f[1] = b; return t.u;
}
__device__ __forceinline__ void u2f(ull v, float& a, float& b) {
    union { float f[2]; ull u; } t; t.u = v; a = t.f[0]; b = t.f[1];
}
__device__ __forceinline__ ull fma2(ull a, ull b, ull c) {
    ull d; asm("fma.rn.f32x2 %0, %1, %2, %3;" : "=l"(d) : "l"(a), "l"(b), "l"(c)); return d;
}

// Each block: 256 queries (2/thread) vs a 512-ref slice packed into smem.
// Emits per-query partial min of (w_j - 2*dot_j) via one atomicMax(rkey).
// The 1-in-16 self block runs exact 2-min and emits the second smallest.
__global__ void __launch_bounds__(QB, 12) k_knn(const float* __restrict__ xyz,
                                                float* __restrict__ out) {
    __shared__ float4 sA[SLICEP];   // {x0,x1,y0,y1} per ref pair
    __shared__ float4 sB[SLICEP];   // {z0,z1,w0,w1}

    const int b     = blockIdx.y;
    const int slice = blockIdx.z;
    const int tid   = threadIdx.x;

    if (blockIdx.x == 0 && slice == 0 && b == 0 && tid == 0)
        out[0] = 0.0f;                               // re-zeroed every launch

    // load + pack this block's ref slice (2 pairs per thread)
    const float* __restrict__ src = xyz + (size_t)(b * NN + slice * SLICE) * 3;
    #pragma unroll
    for (int k = 0; k < SLICEP / QB; k++) {
        int q = tid + k * QB;
        float x0 = src[6*q+0], y0 = src[6*q+1], z0 = src[6*q+2];
        float x1 = src[6*q+3], y1 = src[6*q+4], z1 = src[6*q+5];
        float w0 = (x0*x0 + y0*y0) + z0*z0;
        float w1 = (x1*x1 + y1*y1) + z1*z1;
        sA[q] = make_float4(x0, x1, y0, y1);
        sB[q] = make_float4(z0, z1, w0, w1);
    }

    const int qbase = blockIdx.x * QBLK + tid;
    ull mx[QPT], my[QPT], mz[QPT];
    #pragma unroll
    for (int k = 0; k < QPT; k++) {
        const float* qp = xyz + (size_t)(b * NN + qbase + k * QB) * 3;
        float qx = qp[0], qy = qp[1], qz = qp[2];
        mx[k] = f2u(-2.0f*qx, -2.0f*qx);
        my[k] = f2u(-2.0f*qy, -2.0f*qy);
        mz[k] = f2u(-2.0f*qz, -2.0f*qz);
    }

    __syncthreads();

    const bool self_block = (slice == (blockIdx.x >> 1));  // QBLK*2 == SLICE
    float part[QPT];

    if (!self_block) {
        // fast path: plain min, 2 accumulators per query (fewer registers)
        float a0[QPT], a1[QPT];
        #pragma unroll
        for (int k = 0; k < QPT; k++) { a0[k] = 3.4e38f; a1[k] = 3.4e38f; }

        #pragma unroll 2
        for (int j = 0; j < SLICEP; j += 2) {
            float4 A0 = sA[j],   B0 = sB[j];
            float4 A1 = sA[j+1], B1 = sB[j+1];
            ull x0 = f2u(A0.x, A0.y), y0 = f2u(A0.z, A0.w);
            ull z0 = f2u(B0.x, B0.y), w0 = f2u(B0.z, B0.w);
            ull x1 = f2u(A1.x, A1.y), y1 = f2u(A1.z, A1.w);
            ull z1 = f2u(B1.x, B1.y), w1 = f2u(B1.z, B1.w);
            #pragma unroll
            for (int k = 0; k < QPT; k++) {
                ull t0 = fma2(mx[k], x0, fma2(my[k], y0, fma2(mz[k], z0, w0)));
                ull t1 = fma2(mx[k], x1, fma2(my[k], y1, fma2(mz[k], z1, w1)));
                float c0, c1, c2, c3;
                u2f(t0, c0, c1); u2f(t1, c2, c3);
                a0[k] = fminf(a0[k], fminf(c0, c2));
                a1[k] = fminf(a1[k], fminf(c1, c3));
            }
        }
        #pragma unroll
        for (int k = 0; k < QPT; k++) part[k] = fminf(a0[k], a1[k]);
    } else {
        // self path: exact 2-min; emit second smallest (min excluding self)
        float s0[QPT], s1[QPT];
        #pragma unroll
        for (int k = 0; k < QPT; k++) { s0[k] = 3.4e38f; s1[k] = 3.4e38f; }

        for (int j = 0; j < SLICEP; j += 2) {
            float4 A0 = sA[j],   B0 = sB[j];
            float4 A1 = sA[j+1], B1 = sB[j+1];
            ull x0 = f2u(A0.x, A0.y), y0 = f2u(A0.z, A0.w);
            ull z0 = f2u(B0.x, B0.y), w0 = f2u(B0.z, B0.w);
            ull x1 = f2u(A1.x, A1.y), y1 = f2u(A1.z, A1.w);
            ull z1 = f2u(B1.x, B1.y), w1 = f2u(B1.z, B1.w);
            #pragma unroll
            for (int k = 0; k < QPT; k++) {
                ull t0 = fma2(mx[k], x0, fma2(my[k], y0, fma2(mz[k], z0, w0)));
                ull t1 = fma2(mx[k], x1, fma2(my[k], y1, fma2(mz[k], z1, w1)));
                float c0, c1, c2, c3;
                u2f(t0, c0, c1); u2f(t1, c2, c3);
                float m1 = fminf(c0, c1), M1 = fmaxf(c0, c1);
                float m2 = fminf(c2, c3), M2 = fmaxf(c2, c3);
                float v0 = fminf(m1, m2);
                float v1 = fminf(fmaxf(m1, m2), fminf(M1, M2));
                float n0 = fminf(v0, s0[k]);
                float tt = fmaxf(v0, s0[k]);
                float uu = fminf(v1, s1[k]);
                s0[k] = n0; s1[k] = fminf(tt, uu);
            }
        }
        #pragma unroll
        for (int k = 0; k < QPT; k++) part[k] = s1[k];
    }

    #pragma unroll
    for (int k = 0; k < QPT; k++)
        atomicMax(&g_key[b * NN + qbase + k * QB], rkey(part[k]));
}

// One block per batch (1024 threads, 8 queries/thread): decode keys, dsum in
// registers, one reduce -> threshold -> masked sum. Resets g_key for replay.
__global__ void __launch_bounds__(1024) k_finish(const float* __restrict__ xyz,
                                                 float* __restrict__ out) {
    __shared__ float sh[32];
    __shared__ float s_thr;
    const int b   = blockIdx.x;
    const int tid = threadIdx.x;
    const int lane = tid & 31, wid = tid >> 5;

    float ds[NN / 1024];
    float local = 0.0f;
    #pragma unroll
    for (int k = 0; k < NN / 1024; k++) {
        int q = k * 1024 + tid;
        uint r = g_key[b * NN + q];
        g_key[b * NN + q] = 0;                        // self-reset for replay
        float m = unrkey(r);

        const float* p = xyz + (size_t)(b * NN + q) * 3;
        float px = p[0], py = p[1], pz = p[2];
        float w = (px*px + py*py) + pz*pz;
        float d2nn = w + m;                           // ||q||^2 + shifted min
        float mself = fmaf(-2.0f*px, px, fmaf(-2.0f*py, py, fmaf(-2.0f*pz, pz, w)));
        float d2self = w + mself;

        ds[k] = sqrtf(fmaxf(d2self, EPS)) + sqrtf(fmaxf(d2nn, EPS));
        local += ds[k];
    }

    // block reduce (1024 threads)
    float v = local;
    #pragma unroll
    for (int o = 16; o; o >>= 1) v += __shfl_down_sync(0xFFFFFFFFu, v, o);
    if (lane == 0) sh[wid] = v;
    __syncthreads();
    if (wid == 0) {
        v = sh[lane];
        #pragma unroll
        for (int o = 16; o; o >>= 1) v += __shfl_down_sync(0xFFFFFFFFu, v, o);
        if (lane == 0) s_thr = (v / (float)NN) * ALPHA;   // mean, then *ALPHA
    }
    __syncthreads();
    float thr = s_thr;

    float s = 0.0f;
    #pragma unroll
    for (int k = 0; k < NN / 1024; k++)
        if (ds[k] > thr) s += ds[k];

    #pragma unroll
    for (int o = 16; o; o >>= 1) s += __shfl_down_sync(0xFFFFFFFFu, s, o);
    if (lane == 0) sh[wid] = s;
    __syncthreads();
    if (wid == 0) {
        s = sh[lane];
        #pragma unroll
        for (int o = 16; o; o >>= 1) s += __shfl_down_sync(0xFFFFFFFFu, s, o);
        if (lane == 0) atomicAdd(out, s);
    }
}

extern "C" void kernel_launch(void* const* d_in, const int* in_sizes, int n_in,
                              void* d_out, int out_size) {
    const float* xyz = (const float*)d_in[0];
    float* out = (float*)d_out;

    dim3 grid(GX, BB, SPLIT);            // 32 x 4 x 16 = 2048 blocks
    k_knn<<<grid, QB>>>(xyz, out);

    k_finish<<<BB, 1024>>>(xyz, out);
}

// round 9
// speedup vs baseline: 1.2582x; 1.0491x over previous
#include <cuda_runtime.h>

#define BB    4
#define NN    8192
#define ALPHA 5.0f
#define EPS   1e-12f

#define SPLIT  16                // ref-dimension split
#define SLICE  (NN / SPLIT)      // 512 refs per block
#define SLICEP (SLICE / 2)       // 256 ref pairs (8 KB smem)
#define QB     128               // threads per knn block
#define QPT    2                 // queries per thread
#define QBLK   (QB * QPT)        // 256 queries per block
#define GX     (NN / QBLK)       // 32 query-groups per batch

#define FB     8                 // finish blocks per batch (8*1024 = NN)

typedef unsigned long long ull;
typedef unsigned int uint;

// Reversed-order float keys: min over floats == max over keys; 0 = identity.
__device__ uint  g_key [BB * NN];   // zero at load; k_dsum self-resets
__device__ float g_dsum[BB * NN];
__device__ float g_bsum[BB];        // zeroed by k_knn each launch

__device__ __forceinline__ uint rkey(float f) {
    uint b = __float_as_uint(f);
    uint u = (b & 0x80000000u) ? ~b : (b | 0x80000000u);  // ascending order
    return ~u;                                            // descending
}
__device__ __forceinline__ float unrkey(uint r) {
    uint u = ~r;
    uint b = (u & 0x80000000u) ? (u & 0x7FFFFFFFu) : ~u;
    return __uint_as_float(b);
}

__device__ __forceinline__ ull f2u(float a, float b) {
    union { float f[2]; ull u; } t; t.f[0] = a; t.f[1] = b; return t.u;
}
__device__ __forceinline__ void u2f(ull v, float& a, float& b) {
    union { float f[2]; ull u; } t; t.u = v; a = t.f[0]; b = t.f[1];
}
__device__ __forceinline__ ull fma2(ull a, ull b, ull c) {
    ull d; asm("fma.rn.f32x2 %0, %1, %2, %3;" : "=l"(d) : "l"(a), "l"(b), "l"(c)); return d;
}

// Each block: 256 queries (2/thread) vs a 512-ref slice packed into smem.
// Emits per-query partial min of (w_j - 2*dot_j) via one atomicMax(rkey).
// The 1-in-16 self block runs exact 2-min and emits the second smallest.
__global__ void __launch_bounds__(QB, 12) k_knn(const float* __restrict__ xyz,
                                                float* __restrict__ out) {
    __shared__ float4 sA[SLICEP];   // {x0,x1,y0,y1} per ref pair
    __shared__ float4 sB[SLICEP];   // {z0,z1,w0,w1}

    const int b     = blockIdx.y;
    const int slice = blockIdx.z;
    const int tid   = threadIdx.x;

    // per-replay resets (ordered before k_dsum/k_loss by kernel boundaries)
    if (blockIdx.x == 0 && slice == 0 && tid == 0) {
        if (b == 0) out[0] = 0.0f;
        g_bsum[b] = 0.0f;
    }

    // load + pack this block's ref slice (2 pairs per thread)
    const float* __restrict__ src = xyz + (size_t)(b * NN + slice * SLICE) * 3;
    #pragma unroll
    for (int k = 0; k < SLICEP / QB; k++) {
        int q = tid + k * QB;
        float x0 = src[6*q+0], y0 = src[6*q+1], z0 = src[6*q+2];
        float x1 = src[6*q+3], y1 = src[6*q+4], z1 = src[6*q+5];
        float w0 = (x0*x0 + y0*y0) + z0*z0;
        float w1 = (x1*x1 + y1*y1) + z1*z1;
        sA[q] = make_float4(x0, x1, y0, y1);
        sB[q] = make_float4(z0, z1, w0, w1);
    }

    const int qbase = blockIdx.x * QBLK + tid;
    ull mx[QPT], my[QPT], mz[QPT];
    #pragma unroll
    for (int k = 0; k < QPT; k++) {
        const float* qp = xyz + (size_t)(b * NN + qbase + k * QB) * 3;
        float qx = qp[0], qy = qp[1], qz = qp[2];
        mx[k] = f2u(-2.0f*qx, -2.0f*qx);
        my[k] = f2u(-2.0f*qy, -2.0f*qy);
        mz[k] = f2u(-2.0f*qz, -2.0f*qz);
    }

    __syncthreads();

    const bool self_block = (slice == (blockIdx.x >> 1));  // QBLK*2 == SLICE
    float part[QPT];

    if (!self_block) {
        // fast path: plain min, 2 accumulators per query
        float a0[QPT], a1[QPT];
        #pragma unroll
        for (int k = 0; k < QPT; k++) { a0[k] = 3.4e38f; a1[k] = 3.4e38f; }

        #pragma unroll 2
        for (int j = 0; j < SLICEP; j += 2) {
            float4 A0 = sA[j],   B0 = sB[j];
            float4 A1 = sA[j+1], B1 = sB[j+1];
            ull x0 = f2u(A0.x, A0.y), y0 = f2u(A0.z, A0.w);
            ull z0 = f2u(B0.x, B0.y), w0 = f2u(B0.z, B0.w);
            ull x1 = f2u(A1.x, A1.y), y1 = f2u(A1.z, A1.w);
            ull z1 = f2u(B1.x, B1.y), w1 = f2u(B1.z, B1.w);
            #pragma unroll
            for (int k = 0; k < QPT; k++) {
                ull t0 = fma2(mx[k], x0, fma2(my[k], y0, fma2(mz[k], z0, w0)));
                ull t1 = fma2(mx[k], x1, fma2(my[k], y1, fma2(mz[k], z1, w1)));
                float c0, c1, c2, c3;
                u2f(t0, c0, c1); u2f(t1, c2, c3);
                a0[k] = fminf(a0[k], fminf(c0, c2));
                a1[k] = fminf(a1[k], fminf(c1, c3));
            }
        }
        #pragma unroll
        for (int k = 0; k < QPT; k++) part[k] = fminf(a0[k], a1[k]);
    } else {
        // self path: exact 2-min; emit second smallest (min excluding self)
        float s0[QPT], s1[QPT];
        #pragma unroll
        for (int k = 0; k < QPT; k++) { s0[k] = 3.4e38f; s1[k] = 3.4e38f; }

        for (int j = 0; j < SLICEP; j += 2) {
            float4 A0 = sA[j],   B0 = sB[j];
            float4 A1 = sA[j+1], B1 = sB[j+1];
            ull x0 = f2u(A0.x, A0.y), y0 = f2u(A0.z, A0.w);
            ull z0 = f2u(B0.x, B0.y), w0 = f2u(B0.z, B0.w);
            ull x1 = f2u(A1.x, A1.y), y1 = f2u(A1.z, A1.w);
            ull z1 = f2u(B1.x, B1.y), w1 = f2u(B1.z, B1.w);
            #pragma unroll
            for (int k = 0; k < QPT; k++) {
                ull t0 = fma2(mx[k], x0, fma2(my[k], y0, fma2(mz[k], z0, w0)));
                ull t1 = fma2(mx[k], x1, fma2(my[k], y1, fma2(mz[k], z1, w1)));
                float c0, c1, c2, c3;
                u2f(t0, c0, c1); u2f(t1, c2, c3);
                float m1 = fminf(c0, c1), M1 = fmaxf(c0, c1);
                float m2 = fminf(c2, c3), M2 = fmaxf(c2, c3);
                float v0 = fminf(m1, m2);
                float v1 = fminf(fmaxf(m1, m2), fminf(M1, M2));
                float n0 = fminf(v0, s0[k]);
                float tt = fmaxf(v0, s0[k]);
                float uu = fminf(v1, s1[k]);
                s0[k] = n0; s1[k] = fminf(tt, uu);
            }
        }
        #pragma unroll
        for (int k = 0; k < QPT; k++) part[k] = s1[k];
    }

    #pragma unroll
    for (int k = 0; k < QPT; k++)
        atomicMax(&g_key[b * NN + qbase + k * QB], rkey(part[k]));
}

__device__ __forceinline__ float reduce1024(float v, float* sh) {
    int lane = threadIdx.x & 31, wid = threadIdx.x >> 5;
    #pragma unroll
    for (int o = 16; o; o >>= 1) v += __shfl_down_sync(0xFFFFFFFFu, v, o);
    if (lane == 0) sh[wid] = v;
    __syncthreads();
    if (wid == 0) {
        v = sh[lane];
        #pragma unroll
        for (int o = 16; o; o >>= 1) v += __shfl_down_sync(0xFFFFFFFFu, v, o);
    }
    return v;   // valid in thread 0
}

// grid (FB, BB) x 1024: one point/thread. Decode key (+reset), dsum, batch sum.
__global__ void __launch_bounds__(1024) k_dsum(const float* __restrict__ xyz) {
    __shared__ float sh[32];
    const int b = blockIdx.y;
    const int q = blockIdx.x * 1024 + threadIdx.x;
    const int i = b * NN + q;

    uint r = g_key[i];
    g_key[i] = 0;                                   // self-reset for replay
    float m = unrkey(r);

    const float* p = xyz + (size_t)i * 3;
    float px = p[0], py = p[1], pz = p[2];
    float w = (px*px + py*py) + pz*pz;
    float d2nn = w + m;                             // ||q||^2 + shifted min
    float mself = fmaf(-2.0f*px, px, fmaf(-2.0f*py, py, fmaf(-2.0f*pz, pz, w)));
    float d2self = w + mself;

    float ds = sqrtf(fmaxf(d2self, EPS)) + sqrtf(fmaxf(d2nn, EPS));
    g_dsum[i] = ds;

    float t = reduce1024(ds, sh);
    if (threadIdx.x == 0) atomicAdd(&g_bsum[b], t);
}

// grid (FB, BB) x 1024: threshold (bsum final at kernel boundary), masked sum.
__global__ void __launch_bounds__(1024) k_loss(float* __restrict__ out) {
    __shared__ float sh[32];
    const int b = blockIdx.y;
    const int i = b * NN + blockIdx.x * 1024 + threadIdx.x;

    float thr = (g_bsum[b] / (float)NN) * ALPHA;    // mean, then *ALPHA (ref order)
    float d = g_dsum[i];
    float s = (d > thr) ? d : 0.0f;
    s = reduce1024(s, sh);
    if (threadIdx.x == 0) atomicAdd(out, s);
}

extern "C" void kernel_launch(void* const* d_in, const int* in_sizes, int n_in,
                              void* d_out, int out_size) {
    const float* xyz = (const float*)d_in[0];
    float* out = (float*)d_out;

    dim3 grid(GX, BB, SPLIT);            // 32 x 4 x 16 = 2048 blocks
    k_knn<<<grid, QB>>>(xyz, out);

    dim3 fgrid(FB, BB);                  // 32 wide finish blocks
    k_dsum<<<fgrid, 1024>>>(xyz);
    k_loss<<<fgrid, 1024>>>(out);
}